// round 2
// baseline (speedup 1.0000x reference)
#include <cuda_runtime.h>
#include <cuda_bf16.h>

// Fused SSIM: 5 separable 11x11 Gaussian convs + SSIM map + mean.
// R2: f32x2 packed math (FFMA2), interleaved float2 smem rows (LDS.64),
//     cross-product precomputed at load, sync per 2 rows, tight 138 steps.

#define IMG_W 512
#define IMG_H 512
#define PLANE_STRIDE (512*512)
#define BW 128
#define BH 128
#define NBLOCKS 768          // 48 planes * 4 * 4 tiles
#define C1_CONST 0.0001f
#define C2_CONST 0.0009f

#define W0 0.00102838f
#define W1 0.00759876f
#define W2 0.03600077f
#define W3 0.10936080f
#define W4 0.21300555f
#define W5 0.26601174f

typedef unsigned long long ull;

__device__ __forceinline__ void fma2(ull &d, ull a, ull b, ull c) {
    asm("fma.rn.f32x2 %0, %1, %2, %3;" : "=l"(d) : "l"(a), "l"(b), "l"(c));
}
__device__ __forceinline__ ull mul2(ull a, ull b) {
    ull d; asm("mul.rn.f32x2 %0, %1, %2;" : "=l"(d) : "l"(a), "l"(b)); return d;
}
__device__ __forceinline__ ull pack2(float lo, float hi) {
    ull d; asm("mov.b64 %0, {%1, %2};" : "=l"(d) : "f"(lo), "f"(hi)); return d;
}
__device__ __forceinline__ void unpack2(ull v, float &lo, float &hi) {
    asm("mov.b64 {%0, %1}, %2;" : "=f"(lo), "=f"(hi) : "l"(v));
}

__device__ float g_partial[NBLOCKS];

__global__ void __launch_bounds__(BW)
ssim_main_kernel(const float* __restrict__ img1, const float* __restrict__ img2) {
    __shared__ float2 Ps[4][144];   // (img1, img2) pairs, rows ring
    __shared__ float  Xs[4][144];   // img1*img2, rows ring
    __shared__ float  wsum[4];

    const int t  = threadIdx.x;
    const int b  = blockIdx.x;
    const int plane = b >> 4;
    const int x0 = (b & 3) * BW;
    const int y0 = ((b >> 2) & 3) * BH;

    const float* p1 = img1 + (size_t)plane * PLANE_STRIDE;
    const float* p2 = img2 + (size_t)plane * PLANE_STRIDE;

    const float wgt[6] = {W0, W1, W2, W3, W4, W5};
    ull WQ[6];
    WQ[0] = pack2(W0, W0); WQ[1] = pack2(W1, W1); WQ[2] = pack2(W2, W2);
    WQ[3] = pack2(W3, W3); WQ[4] = pack2(W4, W4); WQ[5] = pack2(W5, W5);

    // vertical scatter rings (all constant-indexed -> registers)
    ull accA[11], accB[11]; float accX[11];
#pragma unroll
    for (int j = 0; j < 11; ++j) { accA[j] = 0ull; accB[j] = 0ull; accX[j] = 0.f; }
    float lsum = 0.f;

    auto load_row = [&](int step) {
        const int slot = step & 3;
        const int r    = y0 - 5 + step;
        const bool rok = ((unsigned)r < (unsigned)IMG_H) && (step < BH + 10);
        const float* q1 = p1 + (size_t)(rok ? r : 0) * IMG_W;
        const float* q2 = p2 + (size_t)(rok ? r : 0) * IMG_W;
        {
            const int xg  = x0 - 5 + t;
            const bool cok = (unsigned)xg < (unsigned)IMG_W;
            const int  xc  = cok ? xg : 0;
            const bool ok  = rok && cok;
            const float a = ok ? q1[xc] : 0.f;
            const float c = ok ? q2[xc] : 0.f;
            Ps[slot][t] = make_float2(a, c);
            Xs[slot][t] = a * c;
        }
        if (t < 10) {
            const int i   = t + BW;
            const int xg  = x0 - 5 + i;      // >= 123, never negative
            const bool cok = xg < IMG_W;
            const int  xc  = cok ? xg : 0;
            const bool ok  = rok && cok;
            const float a = ok ? q1[xc] : 0.f;
            const float c = ok ? q2[xc] : 0.f;
            Ps[slot][i] = make_float2(a, c);
            Xs[slot][i] = a * c;
        }
    };

#define PROC(SV, RR) {                                                        \
    const int slot_ = (SV) & 3;                                               \
    const ull*   rp = reinterpret_cast<const ull*>(&Ps[slot_][0]);            \
    const float* rx = &Xs[slot_][0];                                          \
    ull hmu = 0ull, hsq = 0ull; float hx = 0.f;                               \
    _Pragma("unroll")                                                         \
    for (int k = 0; k < 11; ++k) {                                            \
        const int wi = (k < 6) ? k : 10 - k;                                  \
        const ull ac = rp[t + k];                                             \
        fma2(hmu, ac, WQ[wi], hmu);                                           \
        const ull sq = mul2(ac, ac);                                          \
        fma2(hsq, sq, WQ[wi], hsq);                                           \
        hx = fmaf(rx[t + k], wgt[wi], hx);                                    \
    }                                                                         \
    _Pragma("unroll")                                                         \
    for (int j = 0; j < 11; ++j) {                                            \
        const int wi = (j < 6) ? j : 10 - j;                                  \
        const int sl = ((RR) + j) % 11;                                       \
        fma2(accA[sl], hmu, WQ[wi], accA[sl]);                                \
        fma2(accB[sl], hsq, WQ[wi], accB[sl]);                                \
        accX[sl] = fmaf(hx, wgt[wi], accX[sl]);                               \
    }                                                                         \
    if ((SV) >= 10) {                                                         \
        float mu1, mu2, e11, e22;                                             \
        unpack2(accA[RR], mu1, mu2);                                          \
        unpack2(accB[RR], e11, e22);                                          \
        const float e12 = accX[RR];                                           \
        const float m11 = mu1 * mu1, m22 = mu2 * mu2, m12 = mu1 * mu2;        \
        const float num = (2.f * m12 + C1_CONST) * (2.f * (e12 - m12) + C2_CONST); \
        const float den = (m11 + m22 + C1_CONST) *                            \
                          ((e11 - m11) + (e22 - m22) + C2_CONST);             \
        lsum += __fdividef(num, den);                                         \
    }                                                                         \
    accA[RR] = 0ull; accB[RR] = 0ull; accX[RR] = 0.f;                         \
}

    load_row(0);
    load_row(1);

    int s = 0;
#pragma unroll 1
    for (int blk = 0; blk < 6; ++blk) {     // 6 * 22 = 132 rows
#pragma unroll
        for (int h2 = 0; h2 < 11; ++h2) {   // 2 rows per sync
            __syncthreads();
            load_row(s + 2);
            load_row(s + 3);
            PROC(s,     (2 * h2) % 11);
            PROC(s + 1, (2 * h2 + 1) % 11);
            s += 2;
        }
    }
    // tail rows 132..137  (132 % 11 == 0 and 132 % 4 == 0 keep patterns aligned)
#pragma unroll
    for (int h2 = 0; h2 < 3; ++h2) {
        __syncthreads();
        load_row(s + 2);
        load_row(s + 3);
        PROC(s,     (2 * h2) % 11);
        PROC(s + 1, (2 * h2 + 1) % 11);
        s += 2;
    }
#undef PROC

    // deterministic block reduction
    float v = lsum;
#pragma unroll
    for (int o = 16; o; o >>= 1) v += __shfl_xor_sync(0xffffffffu, v, o);
    if ((t & 31) == 0) wsum[t >> 5] = v;
    __syncthreads();
    if (t == 0) g_partial[b] = wsum[0] + wsum[1] + wsum[2] + wsum[3];
}

__global__ void ssim_reduce_kernel(float* __restrict__ out) {
    const int t = threadIdx.x;   // 32 threads
    float s = 0.f;
#pragma unroll
    for (int i = 0; i < NBLOCKS / 32; ++i) s += g_partial[t + 32 * i];
#pragma unroll
    for (int o = 16; o; o >>= 1) s += __shfl_xor_sync(0xffffffffu, s, o);
    if (t == 0) out[0] = s * (1.0f / 12582912.0f);
}

extern "C" void kernel_launch(void* const* d_in, const int* in_sizes, int n_in,
                              void* d_out, int out_size) {
    const float* img1 = (const float*)d_in[0];
    const float* img2 = (const float*)d_in[1];
    (void)in_sizes; (void)n_in; (void)out_size;
    ssim_main_kernel<<<NBLOCKS, BW>>>(img1, img2);
    ssim_reduce_kernel<<<1, 32>>>((float*)d_out);
}

// round 6
// speedup vs baseline: 1.3978x; 1.3978x over previous
#include <cuda_runtime.h>
#include <cuda_bf16.h>

// Fused SSIM, R3: 4 conv quantities (a, c, ac, a^2+c^2), float4 smem rows,
// even/odd deinterleave, 2 output px per thread, 64 threads/CTA,
// sync every 2 rows, register vertical ring.

#define IMG_W 512
#define IMG_H 512
#define PLANE_STRIDE (512*512)
#define BW 128               // output strip width per CTA
#define NTHR 64              // threads per CTA (2 px each)
#define NBLOCKS 768          // 48 planes * 4x4 tiles
#define NSTEPS 138
#define C1_CONST 0.0001f
#define C2_CONST 0.0009f

#define W0 0.00102838f
#define W1 0.00759876f
#define W2 0.03600077f
#define W3 0.10936080f
#define W4 0.21300555f
#define W5 0.26601174f

__device__ float g_partial[NBLOCKS];

__device__ __forceinline__ float gwt(int k) {
    switch (k) {
        case 0: case 10: return W0;
        case 1: case 9:  return W1;
        case 2: case 8:  return W2;
        case 3: case 7:  return W3;
        case 4: case 6:  return W4;
        default:         return W5;
    }
}

__device__ __forceinline__ void f4fma(float4 &a, const float4 v, const float w) {
    a.x = fmaf(v.x, w, a.x);
    a.y = fmaf(v.y, w, a.y);
    a.z = fmaf(v.z, w, a.z);
    a.w = fmaf(v.w, w, a.w);
}

__global__ void __launch_bounds__(NTHR, 6)
ssim_main_kernel(const float* __restrict__ img1, const float* __restrict__ img2) {
    // 4-row ring; input px p stored: even p -> Ev[(p+6)/2], odd p -> Od[(p+5)/2]
    __shared__ float4 Ev[4][72];
    __shared__ float4 Od[4][72];
    __shared__ float  wsum[2];

    const int t  = threadIdx.x;
    const int b  = blockIdx.x;
    const int plane = b >> 4;
    const int x0 = (b & 3) * BW;
    const int y0 = ((b >> 2) & 3) * BW;

    const float* p1 = img1 + (size_t)plane * PLANE_STRIDE;
    const float* p2 = img2 + (size_t)plane * PLANE_STRIDE;

    // vertical scatter rings for the two output columns (2t, 2t+1)
    float4 accA[11], accB[11];
#pragma unroll
    for (int j = 0; j < 11; ++j) {
        accA[j] = make_float4(0.f, 0.f, 0.f, 0.f);
        accB[j] = make_float4(0.f, 0.f, 0.f, 0.f);
    }
    float lsum = 0.f;

    auto load_row = [&](int step) {
        const int slot = step & 3;
        const int r    = y0 - 5 + step;
        const bool rok = ((unsigned)r < (unsigned)IMG_H) && (step < NSTEPS);
        const float* q1 = p1 + (size_t)(rok ? r : 0) * IMG_W;
        const float* q2 = p2 + (size_t)(rok ? r : 0) * IMG_W;
        {
            const int gx = x0 - 6 + 2 * t;          // even px p = 2t-6
            const bool k0 = rok && ((unsigned)gx       < (unsigned)IMG_W);
            const bool k1 = rok && ((unsigned)(gx + 1) < (unsigned)IMG_W);
            const float a0 = k0 ? __ldg(q1 + gx)     : 0.f;
            const float c0 = k0 ? __ldg(q2 + gx)     : 0.f;
            const float a1 = k1 ? __ldg(q1 + gx + 1) : 0.f;
            const float c1 = k1 ? __ldg(q2 + gx + 1) : 0.f;
            Ev[slot][t] = make_float4(a0, c0, a0 * c0, fmaf(a0, a0, c0 * c0));
            Od[slot][t] = make_float4(a1, c1, a1 * c1, fmaf(a1, a1, c1 * c1));
        }
        if (t < 6) {                                 // tail px 122..133
            const int gx = x0 + 122 + 2 * t;
            const bool k0 = rok && (gx     < IMG_W);
            const bool k1 = rok && (gx + 1 < IMG_W);
            const float a0 = k0 ? __ldg(q1 + gx)     : 0.f;
            const float c0 = k0 ? __ldg(q2 + gx)     : 0.f;
            const float a1 = k1 ? __ldg(q1 + gx + 1) : 0.f;
            const float c1 = k1 ? __ldg(q2 + gx + 1) : 0.f;
            Ev[slot][64 + t] = make_float4(a0, c0, a0 * c0, fmaf(a0, a0, c0 * c0));
            Od[slot][64 + t] = make_float4(a1, c1, a1 * c1, fmaf(a1, a1, c1 * c1));
        }
    };

    auto epi = [&](const float4 q) {   // q = (mu1, mu2, e12, e11+e22)
        const float m11 = q.x * q.x;
        const float m22 = q.y * q.y;
        const float m12 = q.x * q.y;
        const float num = (2.f * m12 + C1_CONST) * (2.f * (q.z - m12) + C2_CONST);
        const float den = (m11 + m22 + C1_CONST) * ((q.w - m11 - m22) + C2_CONST);
        lsum += __fdividef(num, den);
    };

#define PROC(SV, RR) {                                                         \
    const int sl_ = (SV) & 3;                                                  \
    const float4* ev = Ev[sl_];                                                \
    const float4* od = Od[sl_];                                                \
    float4 hA = make_float4(0.f, 0.f, 0.f, 0.f);                               \
    float4 hB = make_float4(0.f, 0.f, 0.f, 0.f);                               \
    float4 v_;                                                                 \
    v_ = od[t];     f4fma(hA, v_, W0);                                         \
    v_ = ev[t + 1]; f4fma(hA, v_, W1); f4fma(hB, v_, W0);                      \
    v_ = od[t + 1]; f4fma(hA, v_, W2); f4fma(hB, v_, W1);                      \
    v_ = ev[t + 2]; f4fma(hA, v_, W3); f4fma(hB, v_, W2);                      \
    v_ = od[t + 2]; f4fma(hA, v_, W4); f4fma(hB, v_, W3);                      \
    v_ = ev[t + 3]; f4fma(hA, v_, W5); f4fma(hB, v_, W4);                      \
    v_ = od[t + 3]; f4fma(hA, v_, W4); f4fma(hB, v_, W5);                      \
    v_ = ev[t + 4]; f4fma(hA, v_, W3); f4fma(hB, v_, W4);                      \
    v_ = od[t + 4]; f4fma(hA, v_, W2); f4fma(hB, v_, W3);                      \
    v_ = ev[t + 5]; f4fma(hA, v_, W1); f4fma(hB, v_, W2);                      \
    v_ = od[t + 5]; f4fma(hA, v_, W0); f4fma(hB, v_, W1);                      \
    v_ = ev[t + 6];                    f4fma(hB, v_, W0);                      \
    _Pragma("unroll")                                                          \
    for (int j = 0; j < 11; ++j) {                                             \
        const float w = gwt(j);                                                \
        const int sl = ((RR) + j) % 11;                                        \
        f4fma(accA[sl], hA, w);                                                \
        f4fma(accB[sl], hB, w);                                                \
    }                                                                          \
    if ((SV) >= 10) { epi(accA[RR]); epi(accB[RR]); }                          \
    accA[RR] = make_float4(0.f, 0.f, 0.f, 0.f);                                \
    accB[RR] = make_float4(0.f, 0.f, 0.f, 0.f);                                \
}

    load_row(0);
    load_row(1);

    int s = 0;
#pragma unroll 1
    for (int blk = 0; blk < 6; ++blk) {          // 6 * 22 = 132 rows
#pragma unroll
        for (int it = 0; it < 11; ++it) {
            __syncthreads();
            load_row(s + 2);
            load_row(s + 3);
            PROC(s,     (2 * it) % 11);
            PROC(s + 1, (2 * it + 1) % 11);
            s += 2;
        }
    }
#pragma unroll
    for (int it = 0; it < 3; ++it) {             // rows 132..137
        __syncthreads();
        load_row(s + 2);
        load_row(s + 3);
        PROC(s,     2 * it);
        PROC(s + 1, 2 * it + 1);
        s += 2;
    }
#undef PROC

    // deterministic block reduction (2 warps)
    float v = lsum;
#pragma unroll
    for (int o = 16; o; o >>= 1) v += __shfl_xor_sync(0xffffffffu, v, o);
    if ((t & 31) == 0) wsum[t >> 5] = v;
    __syncthreads();
    if (t == 0) g_partial[b] = wsum[0] + wsum[1];
}

__global__ void ssim_reduce_kernel(float* __restrict__ out) {
    __shared__ float sm[8];
    const int t = threadIdx.x;   // 256 threads
    float s = g_partial[t] + g_partial[t + 256] + g_partial[t + 512];
#pragma unroll
    for (int o = 16; o; o >>= 1) s += __shfl_xor_sync(0xffffffffu, s, o);
    if ((t & 31) == 0) sm[t >> 5] = s;
    __syncthreads();
    if (t < 32) {
        float v = (t < 8) ? sm[t] : 0.f;
#pragma unroll
        for (int o = 4; o; o >>= 1) v += __shfl_xor_sync(0xffffffffu, v, o);
        if (t == 0) out[0] = v * (1.0f / 12582912.0f);
    }
}

extern "C" void kernel_launch(void* const* d_in, const int* in_sizes, int n_in,
                              void* d_out, int out_size) {
    const float* img1 = (const float*)d_in[0];
    const float* img2 = (const float*)d_in[1];
    (void)in_sizes; (void)n_in; (void)out_size;
    ssim_main_kernel<<<NBLOCKS, NTHR>>>(img1, img2);
    ssim_reduce_kernel<<<1, 256>>>((float*)d_out);
}

// round 7
// speedup vs baseline: 1.5870x; 1.1354x over previous
#include <cuda_runtime.h>
#include <cuda_bf16.h>

// Fused SSIM, R4: R3 algorithm (4 conv quantities, float4 smem, even/odd
// deinterleave, 2 px/thread, register vertical ring) with 4-warp CTAs
// (256-wide strips) so all 4 SMSPs are fed.

#define IMG_W 512
#define IMG_H 512
#define PLANE_STRIDE (512*512)
#define BW 256               // output strip width per CTA
#define NTHR 128             // threads per CTA (2 px each)
#define NBLOCKS 384          // 48 planes * 2x4 tiles
#define NSTEPS 138
#define C1_CONST 0.0001f
#define C2_CONST 0.0009f

#define W0 0.00102838f
#define W1 0.00759876f
#define W2 0.03600077f
#define W3 0.10936080f
#define W4 0.21300555f
#define W5 0.26601174f

__device__ float g_partial[NBLOCKS];

__device__ __forceinline__ float gwt(int k) {
    switch (k) {
        case 0: case 10: return W0;
        case 1: case 9:  return W1;
        case 2: case 8:  return W2;
        case 3: case 7:  return W3;
        case 4: case 6:  return W4;
        default:         return W5;
    }
}

__device__ __forceinline__ void f4fma(float4 &a, const float4 v, const float w) {
    a.x = fmaf(v.x, w, a.x);
    a.y = fmaf(v.y, w, a.y);
    a.z = fmaf(v.z, w, a.z);
    a.w = fmaf(v.w, w, a.w);
}

__global__ void __launch_bounds__(NTHR, 3)
ssim_main_kernel(const float* __restrict__ img1, const float* __restrict__ img2) {
    // 4-row ring; input px p (relative): even p -> Ev[(p+6)/2], odd p -> Od[(p+5)/2]
    __shared__ float4 Ev[4][136];
    __shared__ float4 Od[4][136];
    __shared__ float  wsum[4];

    const int t  = threadIdx.x;
    const int b  = blockIdx.x;
    const int plane = b >> 3;             // 8 tiles per plane
    const int x0 = (b & 1) * BW;
    const int y0 = ((b >> 1) & 3) * 128;

    const float* p1 = img1 + (size_t)plane * PLANE_STRIDE;
    const float* p2 = img2 + (size_t)plane * PLANE_STRIDE;

    // vertical scatter rings for the two output columns (2t, 2t+1)
    float4 accA[11], accB[11];
#pragma unroll
    for (int j = 0; j < 11; ++j) {
        accA[j] = make_float4(0.f, 0.f, 0.f, 0.f);
        accB[j] = make_float4(0.f, 0.f, 0.f, 0.f);
    }
    float lsum = 0.f;

    auto load_row = [&](int step) {
        const int slot = step & 3;
        const int r    = y0 - 5 + step;
        const bool rok = ((unsigned)r < (unsigned)IMG_H) && (step < NSTEPS);
        const float* q1 = p1 + (size_t)(rok ? r : 0) * IMG_W;
        const float* q2 = p2 + (size_t)(rok ? r : 0) * IMG_W;
        {
            const int gx = x0 - 6 + 2 * t;          // even px = 2t-6 (rel)
            const bool k0 = rok && ((unsigned)gx       < (unsigned)IMG_W);
            const bool k1 = rok && ((unsigned)(gx + 1) < (unsigned)IMG_W);
            const float a0 = k0 ? __ldg(q1 + gx)     : 0.f;
            const float c0 = k0 ? __ldg(q2 + gx)     : 0.f;
            const float a1 = k1 ? __ldg(q1 + gx + 1) : 0.f;
            const float c1 = k1 ? __ldg(q2 + gx + 1) : 0.f;
            Ev[slot][t] = make_float4(a0, c0, a0 * c0, fmaf(a0, a0, c0 * c0));
            Od[slot][t] = make_float4(a1, c1, a1 * c1, fmaf(a1, a1, c1 * c1));
        }
        if (t < 6) {                                 // tail px 250..261 (rel)
            const int gx = x0 + 250 + 2 * t;
            const bool k0 = rok && (gx     < IMG_W);
            const bool k1 = rok && (gx + 1 < IMG_W);
            const float a0 = k0 ? __ldg(q1 + gx)     : 0.f;
            const float c0 = k0 ? __ldg(q2 + gx)     : 0.f;
            const float a1 = k1 ? __ldg(q1 + gx + 1) : 0.f;
            const float c1 = k1 ? __ldg(q2 + gx + 1) : 0.f;
            Ev[slot][128 + t] = make_float4(a0, c0, a0 * c0, fmaf(a0, a0, c0 * c0));
            Od[slot][128 + t] = make_float4(a1, c1, a1 * c1, fmaf(a1, a1, c1 * c1));
        }
    };

    auto epi = [&](const float4 q) {   // q = (mu1, mu2, e12, e11+e22)
        const float m11 = q.x * q.x;
        const float m22 = q.y * q.y;
        const float m12 = q.x * q.y;
        const float num = (2.f * m12 + C1_CONST) * (2.f * (q.z - m12) + C2_CONST);
        const float den = (m11 + m22 + C1_CONST) * ((q.w - m11 - m22) + C2_CONST);
        lsum += __fdividef(num, den);
    };

#define PROC(SV, RR) {                                                         \
    const int sl_ = (SV) & 3;                                                  \
    const float4* ev = Ev[sl_];                                                \
    const float4* od = Od[sl_];                                                \
    float4 hA = make_float4(0.f, 0.f, 0.f, 0.f);                               \
    float4 hB = make_float4(0.f, 0.f, 0.f, 0.f);                               \
    float4 v_;                                                                 \
    v_ = od[t];     f4fma(hA, v_, W0);                                         \
    v_ = ev[t + 1]; f4fma(hA, v_, W1); f4fma(hB, v_, W0);                      \
    v_ = od[t + 1]; f4fma(hA, v_, W2); f4fma(hB, v_, W1);                      \
    v_ = ev[t + 2]; f4fma(hA, v_, W3); f4fma(hB, v_, W2);                      \
    v_ = od[t + 2]; f4fma(hA, v_, W4); f4fma(hB, v_, W3);                      \
    v_ = ev[t + 3]; f4fma(hA, v_, W5); f4fma(hB, v_, W4);                      \
    v_ = od[t + 3]; f4fma(hA, v_, W4); f4fma(hB, v_, W5);                      \
    v_ = ev[t + 4]; f4fma(hA, v_, W3); f4fma(hB, v_, W4);                      \
    v_ = od[t + 4]; f4fma(hA, v_, W2); f4fma(hB, v_, W3);                      \
    v_ = ev[t + 5]; f4fma(hA, v_, W1); f4fma(hB, v_, W2);                      \
    v_ = od[t + 5]; f4fma(hA, v_, W0); f4fma(hB, v_, W1);                      \
    v_ = ev[t + 6];                    f4fma(hB, v_, W0);                      \
    _Pragma("unroll")                                                          \
    for (int j = 0; j < 11; ++j) {                                             \
        const float w = gwt(j);                                                \
        const int sl = ((RR) + j) % 11;                                        \
        f4fma(accA[sl], hA, w);                                                \
        f4fma(accB[sl], hB, w);                                                \
    }                                                                          \
    if ((SV) >= 10) { epi(accA[RR]); epi(accB[RR]); }                          \
    accA[RR] = make_float4(0.f, 0.f, 0.f, 0.f);                                \
    accB[RR] = make_float4(0.f, 0.f, 0.f, 0.f);                                \
}

    load_row(0);
    load_row(1);

    int s = 0;
#pragma unroll 1
    for (int blk = 0; blk < 6; ++blk) {          // 6 * 22 = 132 rows
#pragma unroll
        for (int it = 0; it < 11; ++it) {
            __syncthreads();
            load_row(s + 2);
            load_row(s + 3);
            PROC(s,     (2 * it) % 11);
            PROC(s + 1, (2 * it + 1) % 11);
            s += 2;
        }
    }
#pragma unroll
    for (int it = 0; it < 3; ++it) {             // rows 132..137
        __syncthreads();
        load_row(s + 2);
        load_row(s + 3);
        PROC(s,     2 * it);
        PROC(s + 1, 2 * it + 1);
        s += 2;
    }
#undef PROC

    // deterministic block reduction (4 warps)
    float v = lsum;
#pragma unroll
    for (int o = 16; o; o >>= 1) v += __shfl_xor_sync(0xffffffffu, v, o);
    if ((t & 31) == 0) wsum[t >> 5] = v;
    __syncthreads();
    if (t == 0) g_partial[b] = wsum[0] + wsum[1] + wsum[2] + wsum[3];
}

__global__ void ssim_reduce_kernel(float* __restrict__ out) {
    __shared__ float sm[4];
    const int t = threadIdx.x;   // 128 threads
    float s = g_partial[t] + g_partial[t + 128] + g_partial[t + 256];
#pragma unroll
    for (int o = 16; o; o >>= 1) s += __shfl_xor_sync(0xffffffffu, s, o);
    if ((t & 31) == 0) sm[t >> 5] = s;
    __syncthreads();
    if (t < 32) {
        float v = (t < 4) ? sm[t] : 0.f;
#pragma unroll
        for (int o = 2; o; o >>= 1) v += __shfl_xor_sync(0xffffffffu, v, o);
        if (t == 0) out[0] = v * (1.0f / 12582912.0f);
    }
}

extern "C" void kernel_launch(void* const* d_in, const int* in_sizes, int n_in,
                              void* d_out, int out_size) {
    const float* img1 = (const float*)d_in[0];
    const float* img2 = (const float*)d_in[1];
    (void)in_sizes; (void)n_in; (void)out_size;
    ssim_main_kernel<<<NBLOCKS, NTHR>>>(img1, img2);
    ssim_reduce_kernel<<<1, 128>>>((float*)d_out);
}